// round 2
// baseline (speedup 1.0000x reference)
#include <cuda_runtime.h>

#define BATCH   2
#define HEADS   16
#define SEQ     2048
#define DKV     64
#define DMODEL  1024
#define MTOT    (BATCH * SEQ)      // 4096 rows
#define BIAS_PAD    4352
#define BIAS_CENTER 2176

#define QR 128   // q rows per attention CTA (1 per thread)
#define KT 32    // k rows per inner tile

// ---------------- scratch (device globals: allocation-guard safe) ----------
__device__ float g_q[BATCH * HEADS * SEQ * DKV];
__device__ float g_k[BATCH * HEADS * SEQ * DKV];
__device__ float g_v[BATCH * HEADS * SEQ * DKV];
__device__ float g_attn[MTOT * DMODEL];
__device__ float g_bias[HEADS * BIAS_PAD];

// ---------------- T5 relative-position bias, per head per delta -------------
__global__ void bias_kernel(const float* __restrict__ table) {
    int i = blockIdx.x * blockDim.x + threadIdx.x;
    if (i >= HEADS * BIAS_PAD) return;
    int h = i / BIAS_PAD;
    int delta = (i % BIAS_PAD) - BIAS_CENTER;   // delta = k - q
    float v = 0.0f;
    int rp = delta < 0 ? -delta : delta;
    if (rp <= SEQ - 1) {
        int base = (delta > 0) ? 16 : 0;
        int bucket;
        if (rp < 8) {
            bucket = base + rp;
        } else {
            // mirrors jnp: 8 + int32(log(rp/8)/log(16) * 8), clamped to 15
            float ratio = logf((float)rp * 0.125f) / (float)2.772588722239781;
            int rpl = 8 + (int)(ratio * 8.0f);
            bucket = base + (rpl < 15 ? rpl : 15);
        }
        v = table[bucket * HEADS + h];
    }
    g_bias[i] = v;
}

// ---------------- SGEMM 128x128 tile, BK=8, 8x8 per-thread ------------------
// C[M=4096, N=1024] = A[4096,1024] @ B[1024,1024]
// a_is_gattn: A comes from g_attn instead of Aext
// c_sel: 0 -> Cext (row-major), 1/2/3 -> g_q/g_k/g_v with (b,h,s,d) layout
__global__ __launch_bounds__(256) void sgemm128(const float* __restrict__ Aext,
                                                int a_is_gattn,
                                                const float* __restrict__ B,
                                                float* __restrict__ Cext,
                                                int c_sel, int head_layout) {
    const int K = DMODEL, N = DMODEL;
    const float* A = a_is_gattn ? g_attn : Aext;

    __shared__ __align__(16) float As[8][128];
    __shared__ __align__(16) float Bs[8][128];

    int tid = threadIdx.x;
    int m0 = blockIdx.y * 128;
    int n0 = blockIdx.x * 128;
    int tx = tid & 15;          // 0..15 -> 8 output cols
    int ty = tid >> 4;          // 0..15 -> 8 output rows

    int arow = tid >> 1;        // 0..127
    int acol = (tid & 1) * 4;   // 0 or 4
    int brow = tid >> 5;        // 0..7
    int bcol = (tid & 31) * 4;  // 0..124

    const float* Ap = A + (size_t)(m0 + arow) * K + acol;
    const float* Bp = B + (size_t)brow * N + n0 + bcol;

    float acc[8][8];
#pragma unroll
    for (int i = 0; i < 8; i++)
#pragma unroll
        for (int j = 0; j < 8; j++) acc[i][j] = 0.0f;

    for (int k0 = 0; k0 < K; k0 += 8) {
        float4 av = *(const float4*)Ap; Ap += 8;
        float4 bv = *(const float4*)Bp; Bp += 8 * N;
        As[acol + 0][arow] = av.x;
        As[acol + 1][arow] = av.y;
        As[acol + 2][arow] = av.z;
        As[acol + 3][arow] = av.w;
        *(float4*)&Bs[brow][bcol] = bv;
        __syncthreads();
#pragma unroll
        for (int kk = 0; kk < 8; kk++) {
            float4 a0 = *(const float4*)&As[kk][ty * 8];
            float4 a1 = *(const float4*)&As[kk][ty * 8 + 4];
            float4 b0 = *(const float4*)&Bs[kk][tx * 8];
            float4 b1 = *(const float4*)&Bs[kk][tx * 8 + 4];
            float a[8] = {a0.x, a0.y, a0.z, a0.w, a1.x, a1.y, a1.z, a1.w};
            float b[8] = {b0.x, b0.y, b0.z, b0.w, b1.x, b1.y, b1.z, b1.w};
#pragma unroll
            for (int i = 0; i < 8; i++)
#pragma unroll
                for (int j = 0; j < 8; j++)
                    acc[i][j] = fmaf(a[i], b[j], acc[i][j]);
        }
        __syncthreads();
    }

    float* Cq = (c_sel == 1) ? g_q : (c_sel == 2) ? g_k : g_v;
#pragma unroll
    for (int i = 0; i < 8; i++) {
        int r = m0 + ty * 8 + i;
#pragma unroll
        for (int j = 0; j < 8; j++) {
            int c = n0 + tx * 8 + j;
            float v = acc[i][j];
            if (head_layout) {
                int b = r >> 11;       // r / SEQ
                int s = r & (SEQ - 1);
                int h = c >> 6;        // c / DKV
                int d = c & (DKV - 1);
                Cq[(((size_t)(b * HEADS + h) * SEQ + s) << 6) + d] = v;
            } else {
                Cext[(size_t)r * N + c] = v;
            }
        }
    }
}

// ---------------- flash attention: 1 thread = 1 q row -----------------------
__global__ __launch_bounds__(128) void attn_kernel() {
    int tid = threadIdx.x;
    int qt = blockIdx.x, h = blockIdx.y, b = blockIdx.z;
    int bh = b * HEADS + h;
    int q0 = qt * QR;
    int qi = q0 + tid;

    __shared__ __align__(16) float4 Ks4[KT * 16];   // 32 x 64 f32
    __shared__ __align__(16) float4 Vs4[KT * 16];
    __shared__ float Ss[KT * QR];                   // raw scores, column per thread
    __shared__ float bias_s[KT + QR];               // 160 entries

    float4 q4[16], o4[16];
    const float4* qp = (const float4*)(g_q + (((size_t)bh * SEQ + qi) << 6));
#pragma unroll
    for (int i = 0; i < 16; i++) {
        q4[i] = qp[i];
        o4[i] = make_float4(0.f, 0.f, 0.f, 0.f);
    }

    float m = -1e30f, l = 0.0f;

    for (int kt = 0; kt < SEQ / KT; kt++) {
        int kbase = kt * KT;
        const float4* kp = (const float4*)(g_k + (((size_t)bh * SEQ + kbase) << 6));
        const float4* vp = (const float4*)(g_v + (((size_t)bh * SEQ + kbase) << 6));

        __syncthreads();   // previous iteration's reads done
#pragma unroll
        for (int i = 0; i < 4; i++) {
            Ks4[tid + i * 128] = kp[tid + i * 128];
            Vs4[tid + i * 128] = vp[tid + i * 128];
        }
        {
            // bias_s[t] covers delta = kbase + (t - (QR-1)) - q0
            const float* bb = g_bias + h * BIAS_PAD + (BIAS_CENTER - (QR - 1)) - q0 + kbase;
            bias_s[tid] = bb[tid];
            if (tid < KT) bias_s[QR + tid] = bb[QR + tid];
        }
        __syncthreads();

        // ---- scores: s_j = q . k_j + bias(j - tid) ----
        float mt = -1e30f;
#pragma unroll 4
        for (int j = 0; j < KT; j++) {
            float s0 = 0.f, s1 = 0.f, s2 = 0.f, s3 = 0.f;
#pragma unroll
            for (int d4 = 0; d4 < 16; d4++) {
                float4 kk = Ks4[j * 16 + d4];
                float4 qq = q4[d4];
                s0 = fmaf(qq.x, kk.x, s0);
                s1 = fmaf(qq.y, kk.y, s1);
                s2 = fmaf(qq.z, kk.z, s2);
                s3 = fmaf(qq.w, kk.w, s3);
            }
            float sj = (s0 + s1) + (s2 + s3);
            sj += bias_s[j - tid + (QR - 1)];
            Ss[j * QR + tid] = sj;
            mt = fmaxf(mt, sj);
        }

        // ---- online softmax rescale ----
        float mnew = fmaxf(m, mt);
        float corr = __expf(m - mnew);
#pragma unroll
        for (int i = 0; i < 16; i++) {
            o4[i].x *= corr; o4[i].y *= corr; o4[i].z *= corr; o4[i].w *= corr;
        }

        // ---- P.V accumulate ----
        float ssum = 0.f;
#pragma unroll 4
        for (int j = 0; j < KT; j++) {
            float p = __expf(Ss[j * QR + tid] - mnew);
            ssum += p;
#pragma unroll
            for (int d4 = 0; d4 < 16; d4++) {
                float4 vv = Vs4[j * 16 + d4];
                o4[d4].x = fmaf(p, vv.x, o4[d4].x);
                o4[d4].y = fmaf(p, vv.y, o4[d4].y);
                o4[d4].z = fmaf(p, vv.z, o4[d4].z);
                o4[d4].w = fmaf(p, vv.w, o4[d4].w);
            }
        }
        l = l * corr + ssum;
        m = mnew;
    }

    float inv = 1.0f / l;
    float4* op = (float4*)(g_attn + ((size_t)b * SEQ + qi) * DMODEL + h * DKV);
#pragma unroll
    for (int i = 0; i < 16; i++) {
        float4 v = o4[i];
        v.x *= inv; v.y *= inv; v.z *= inv; v.w *= inv;
        op[i] = v;
    }
}

// ---------------- launcher ---------------------------------------------------
extern "C" void kernel_launch(void* const* d_in, const int* in_sizes, int n_in,
                              void* d_out, int out_size) {
    const float* hidden = (const float*)d_in[0];
    const float* Wq     = (const float*)d_in[1];
    const float* Wk     = (const float*)d_in[2];
    const float* Wv     = (const float*)d_in[3];
    const float* Wo     = (const float*)d_in[4];
    const float* table  = (const float*)d_in[5];
    float* out = (float*)d_out;

    bias_kernel<<<(HEADS * BIAS_PAD + 255) / 256, 256>>>(table);

    dim3 ggrid(DMODEL / 128, MTOT / 128);   // 8 x 32
    sgemm128<<<ggrid, 256>>>(hidden, 0, Wq, nullptr, 1, 1);
    sgemm128<<<ggrid, 256>>>(hidden, 0, Wk, nullptr, 2, 1);
    sgemm128<<<ggrid, 256>>>(hidden, 0, Wv, nullptr, 3, 1);

    attn_kernel<<<dim3(SEQ / QR, HEADS, BATCH), 128>>>();

    sgemm128<<<ggrid, 256>>>(nullptr, 1, Wo, out, 0, 0);
}

// round 3
// speedup vs baseline: 1.0236x; 1.0236x over previous
#include <cuda_runtime.h>

#define BATCH   2
#define HEADS   16
#define SEQ     2048
#define DKV     64
#define DMODEL  1024
#define MTOT    (BATCH * SEQ)      // 4096 rows
#define BIAS_PAD    4352
#define BIAS_CENTER 2176

#define QR 128   // q rows per attention CTA (1 per thread)
#define KT 32    // k rows per inner tile

typedef unsigned long long u64;

// ---------------- packed f32x2 helpers (Blackwell FFMA2 path) --------------
__device__ __forceinline__ u64 pk2(float lo, float hi) {
    u64 r; asm("mov.b64 %0, {%1, %2};" : "=l"(r) : "f"(lo), "f"(hi)); return r;
}
__device__ __forceinline__ void fma2(u64& d, u64 a, u64 b) {
    asm("fma.rn.f32x2 %0, %1, %2, %0;" : "+l"(d) : "l"(a), "l"(b));
}
__device__ __forceinline__ void add2(u64& d, u64 a) {
    asm("add.rn.f32x2 %0, %1, %0;" : "+l"(d) : "l"(a));
}
__device__ __forceinline__ u64 mul2(u64 a, u64 b) {
    u64 r; asm("mul.rn.f32x2 %0, %1, %2;" : "=l"(r) : "l"(a), "l"(b)); return r;
}
__device__ __forceinline__ float2 up2(u64 v) {
    float2 f; asm("mov.b64 {%0, %1}, %2;" : "=f"(f.x), "=f"(f.y) : "l"(v)); return f;
}

// ---------------- scratch (device globals: allocation-guard safe) ----------
__device__ float g_q[BATCH * HEADS * SEQ * DKV];
__device__ float g_k[BATCH * HEADS * SEQ * DKV];
__device__ float g_v[BATCH * HEADS * SEQ * DKV];
__device__ float g_attn[MTOT * DMODEL];
__device__ float g_bias[HEADS * BIAS_PAD];

// ---------------- T5 relative-position bias, per head per delta -------------
__global__ void bias_kernel(const float* __restrict__ table) {
    int i = blockIdx.x * blockDim.x + threadIdx.x;
    if (i >= HEADS * BIAS_PAD) return;
    int h = i / BIAS_PAD;
    int delta = (i % BIAS_PAD) - BIAS_CENTER;   // delta = k - q
    float v = 0.0f;
    int rp = delta < 0 ? -delta : delta;
    if (rp <= SEQ - 1) {
        int base = (delta > 0) ? 16 : 0;
        int bucket;
        if (rp < 8) {
            bucket = base + rp;
        } else {
            // mirrors jnp: 8 + int32(log(rp/8)/log(16) * 8), clamped to 15
            float ratio = logf((float)rp * 0.125f) / (float)2.772588722239781;
            int rpl = 8 + (int)(ratio * 8.0f);
            bucket = base + (rpl < 15 ? rpl : 15);
        }
        v = table[bucket * HEADS + h];
    }
    g_bias[i] = v;
}

// ---------------- SGEMM 128x128 tile, BK=8, 8x8 per-thread, FFMA2 ----------
// C[M=4096, N=1024] = A[4096,1024] @ B[1024,1024]
// qkv_fused: A=hidden, W selected by blockIdx.z, out -> g_q/g_k/g_v head layout
// else:      A=g_attn, W=Wo, out -> Cext row-major
__global__ __launch_bounds__(256) void sgemm128(const float* __restrict__ Aext,
                                                int qkv_fused,
                                                const float* __restrict__ W0,
                                                const float* __restrict__ W1,
                                                const float* __restrict__ W2,
                                                float* __restrict__ Cext) {
    const int K = DMODEL, N = DMODEL;
    int zc = qkv_fused ? blockIdx.z : 0;
    const float* A = qkv_fused ? Aext : g_attn;
    const float* B = (zc == 0) ? W0 : (zc == 1) ? W1 : W2;

    __shared__ __align__(16) float As[8][128];
    __shared__ __align__(16) float Bs[8][128];

    int tid = threadIdx.x;
    int m0 = blockIdx.y * 128;
    int n0 = blockIdx.x * 128;
    int tx = tid & 15;          // 0..15 -> 8 output cols
    int ty = tid >> 4;          // 0..15 -> 8 output rows

    int arow = tid >> 1;        // 0..127
    int acol = (tid & 1) * 4;   // 0 or 4
    int brow = tid >> 5;        // 0..7
    int bcol = (tid & 31) * 4;  // 0..124

    const float* Ap = A + (size_t)(m0 + arow) * K + acol;
    const float* Bp = B + (size_t)brow * N + n0 + bcol;

    u64 acc2[8][4];
#pragma unroll
    for (int i = 0; i < 8; i++)
#pragma unroll
        for (int j = 0; j < 4; j++) acc2[i][j] = 0ull;

    for (int k0 = 0; k0 < K; k0 += 8) {
        float4 av = *(const float4*)Ap; Ap += 8;
        float4 bv = *(const float4*)Bp; Bp += 8 * N;
        As[acol + 0][arow] = av.x;
        As[acol + 1][arow] = av.y;
        As[acol + 2][arow] = av.z;
        As[acol + 3][arow] = av.w;
        *(float4*)&Bs[brow][bcol] = bv;
        __syncthreads();
#pragma unroll
        for (int kk = 0; kk < 8; kk++) {
            float4 a0 = *(const float4*)&As[kk][ty * 8];
            float4 a1 = *(const float4*)&As[kk][ty * 8 + 4];
            // b pairs come packed straight from shared memory
            const ulonglong2* bp2 = (const ulonglong2*)&Bs[kk][tx * 8];
            ulonglong2 bA = bp2[0];
            ulonglong2 bB = bp2[1];
            float a[8] = {a0.x, a0.y, a0.z, a0.w, a1.x, a1.y, a1.z, a1.w};
#pragma unroll
            for (int i = 0; i < 8; i++) {
                u64 a2 = pk2(a[i], a[i]);
                fma2(acc2[i][0], a2, bA.x);
                fma2(acc2[i][1], a2, bA.y);
                fma2(acc2[i][2], a2, bB.x);
                fma2(acc2[i][3], a2, bB.y);
            }
        }
        __syncthreads();
    }

    float* Cq = (zc == 0) ? g_q : (zc == 1) ? g_k : g_v;
#pragma unroll
    for (int i = 0; i < 8; i++) {
        int r = m0 + ty * 8 + i;
#pragma unroll
        for (int j = 0; j < 4; j++) {
            float2 f = up2(acc2[i][j]);
#pragma unroll
            for (int half = 0; half < 2; half++) {
                int c = n0 + tx * 8 + j * 2 + half;
                float v = half ? f.y : f.x;
                if (qkv_fused) {
                    int b = r >> 11;       // r / SEQ
                    int s = r & (SEQ - 1);
                    int h = c >> 6;        // c / DKV
                    int d = c & (DKV - 1);
                    Cq[(((size_t)(b * HEADS + h) * SEQ + s) << 6) + d] = v;
                } else {
                    Cext[(size_t)r * N + c] = v;
                }
            }
        }
    }
}

// ---------------- flash attention: 1 thread = 1 q row, FFMA2 ---------------
__global__ __launch_bounds__(128) void attn_kernel() {
    int tid = threadIdx.x;
    int qt = blockIdx.x, h = blockIdx.y, b = blockIdx.z;
    int bh = b * HEADS + h;
    int q0 = qt * QR;
    int qi = q0 + tid;

    __shared__ __align__(16) u64 Ks2[KT * 32];   // 32 rows x 32 f32-pairs
    __shared__ __align__(16) u64 Vs2[KT * 32];
    __shared__ float Ss[KT * QR];                // raw scores, column per thread
    __shared__ float bias_s[KT + QR];            // 160 entries

    u64 q2[32], o2[32];
    const u64* qp = (const u64*)(g_q + (((size_t)bh * SEQ + qi) << 6));
#pragma unroll
    for (int i = 0; i < 32; i++) {
        q2[i] = qp[i];
        o2[i] = 0ull;       // bit pattern of (0.0f, 0.0f)
    }

    float m = -1e30f, l = 0.0f;

    for (int kt = 0; kt < SEQ / KT; kt++) {
        int kbase = kt * KT;
        const float4* kp = (const float4*)(g_k + (((size_t)bh * SEQ + kbase) << 6));
        const float4* vp = (const float4*)(g_v + (((size_t)bh * SEQ + kbase) << 6));

        __syncthreads();   // previous iteration's reads done
#pragma unroll
        for (int i = 0; i < 4; i++) {
            ((float4*)Ks2)[tid + i * 128] = kp[tid + i * 128];
            ((float4*)Vs2)[tid + i * 128] = vp[tid + i * 128];
        }
        {
            // bias_s[t] covers delta = kbase + (t - (QR-1)) - q0
            const float* bb = g_bias + h * BIAS_PAD + (BIAS_CENTER - (QR - 1)) - q0 + kbase;
            bias_s[tid] = bb[tid];
            if (tid < KT) bias_s[QR + tid] = bb[QR + tid];
        }
        __syncthreads();

        // ---- scores: s_j = q . k_j + bias(j - tid) ----
        float mt = -1e30f;
#pragma unroll 4
        for (int j = 0; j < KT; j++) {
            u64 s0 = 0ull, s1 = 0ull, s2 = 0ull, s3 = 0ull;
            const ulonglong2* kr2 = (const ulonglong2*)&Ks2[j * 32];
#pragma unroll
            for (int t = 0; t < 4; t++) {
                ulonglong2 ka = kr2[t];
                ulonglong2 kb = kr2[t + 4];
                ulonglong2 kc = kr2[t + 8];
                ulonglong2 kd = kr2[t + 12];
                fma2(s0, q2[2 * t],      ka.x); fma2(s0, q2[2 * t + 1],  ka.y);
                fma2(s1, q2[8 + 2 * t],  kb.x); fma2(s1, q2[9 + 2 * t],  kb.y);
                fma2(s2, q2[16 + 2 * t], kc.x); fma2(s2, q2[17 + 2 * t], kc.y);
                fma2(s3, q2[24 + 2 * t], kd.x); fma2(s3, q2[25 + 2 * t], kd.y);
            }
            add2(s0, s1); add2(s2, s3); add2(s0, s2);
            float2 f = up2(s0);
            float sj = f.x + f.y + bias_s[j - tid + (QR - 1)];
            Ss[j * QR + tid] = sj;
            mt = fmaxf(mt, sj);
        }

        // ---- online softmax rescale ----
        float mnew = fmaxf(m, mt);
        float corr = __expf(m - mnew);
        u64 c2 = pk2(corr, corr);
#pragma unroll
        for (int i = 0; i < 32; i++) o2[i] = mul2(o2[i], c2);

        // ---- P.V accumulate ----
        float ssum = 0.f;
#pragma unroll 4
        for (int j = 0; j < KT; j++) {
            float p = __expf(Ss[j * QR + tid] - mnew);
            ssum += p;
            u64 p2 = pk2(p, p);
            const ulonglong2* vr2 = (const ulonglong2*)&Vs2[j * 32];
#pragma unroll
            for (int t = 0; t < 16; t++) {
                ulonglong2 vv = vr2[t];
                fma2(o2[2 * t],     p2, vv.x);
                fma2(o2[2 * t + 1], p2, vv.y);
            }
        }
        l = l * corr + ssum;
        m = mnew;
    }

    float inv = 1.0f / l;
    u64 inv2 = pk2(inv, inv);
    ulonglong2* op = (ulonglong2*)(g_attn + ((size_t)b * SEQ + qi) * DMODEL + h * DKV);
#pragma unroll
    for (int t = 0; t < 16; t++) {
        ulonglong2 w;
        w.x = mul2(o2[2 * t],     inv2);
        w.y = mul2(o2[2 * t + 1], inv2);
        op[t] = w;
    }
}

// ---------------- launcher ---------------------------------------------------
extern "C" void kernel_launch(void* const* d_in, const int* in_sizes, int n_in,
                              void* d_out, int out_size) {
    const float* hidden = (const float*)d_in[0];
    const float* Wq     = (const float*)d_in[1];
    const float* Wk     = (const float*)d_in[2];
    const float* Wv     = (const float*)d_in[3];
    const float* Wo     = (const float*)d_in[4];
    const float* table  = (const float*)d_in[5];
    float* out = (float*)d_out;

    bias_kernel<<<(HEADS * BIAS_PAD + 255) / 256, 256>>>(table);

    // fused QKV projection: z = 0/1/2 -> Wq/Wk/Wv
    dim3 qkv_grid(DMODEL / 128, MTOT / 128, 3);   // 8 x 32 x 3
    sgemm128<<<qkv_grid, 256>>>(hidden, 1, Wq, Wk, Wv, nullptr);

    attn_kernel<<<dim3(SEQ / QR, HEADS, BATCH), 128>>>();

    // output projection
    dim3 o_grid(DMODEL / 128, MTOT / 128, 1);
    sgemm128<<<o_grid, 256>>>(nullptr, 0, Wo, Wo, Wo, out);
}

// round 6
// speedup vs baseline: 1.4415x; 1.4083x over previous
#include <cuda_runtime.h>
#include <cstdint>

#define BATCH   2
#define HEADS   16
#define SEQ     2048
#define DKV     64
#define DMODEL  1024
#define MTOT    (BATCH * SEQ)      // 4096 rows
#define BIAS_PAD    4352
#define BIAS_CENTER 2176

#define QR 128   // q rows per attention CTA (1 per thread)
#define KT 32    // k rows per inner tile

typedef unsigned long long u64;

// ---------------- packed f32x2 helpers (attention) --------------------------
__device__ __forceinline__ u64 pk2(float lo, float hi) {
    u64 r; asm("mov.b64 %0, {%1, %2};" : "=l"(r) : "f"(lo), "f"(hi)); return r;
}
__device__ __forceinline__ void fma2(u64& d, u64 a, u64 b) {
    asm("fma.rn.f32x2 %0, %1, %2, %0;" : "+l"(d) : "l"(a), "l"(b));
}
__device__ __forceinline__ void add2(u64& d, u64 a) {
    asm("add.rn.f32x2 %0, %1, %0;" : "+l"(d) : "l"(a));
}
__device__ __forceinline__ u64 mul2(u64 a, u64 b) {
    u64 r; asm("mul.rn.f32x2 %0, %1, %2;" : "=l"(r) : "l"(a), "l"(b)); return r;
}
__device__ __forceinline__ float2 up2(u64 v) {
    float2 f; asm("mov.b64 {%0, %1}, %2;" : "=f"(f.x), "=f"(f.y) : "l"(v)); return f;
}

// ---------------- bf16 pack + tensor-core helpers ---------------------------
// returns packed b16x2: low half = bf16(lo_e), high half = bf16(hi_e)
__device__ __forceinline__ uint32_t bfpack(float lo_e, float hi_e) {
    uint32_t r; asm("cvt.rn.bf16x2.f32 %0, %1, %2;" : "=r"(r) : "f"(hi_e), "f"(lo_e));
    return r;
}
__device__ __forceinline__ uint32_t smem_u32(const void* p) {
    uint32_t a;
    asm("{ .reg .u64 t; cvta.to.shared.u64 t, %1; cvt.u32.u64 %0, t; }" : "=r"(a) : "l"(p));
    return a;
}
__device__ __forceinline__ void ldm_x4(uint32_t* r, uint32_t addr) {
    asm volatile("ldmatrix.sync.aligned.m8n8.x4.shared.b16 {%0,%1,%2,%3}, [%4];"
        : "=r"(r[0]), "=r"(r[1]), "=r"(r[2]), "=r"(r[3]) : "r"(addr));
}
__device__ __forceinline__ void ldm_x4t(uint32_t* r, uint32_t addr) {
    asm volatile("ldmatrix.sync.aligned.m8n8.x4.trans.shared.b16 {%0,%1,%2,%3}, [%4];"
        : "=r"(r[0]), "=r"(r[1]), "=r"(r[2]), "=r"(r[3]) : "r"(addr));
}
__device__ __forceinline__ void mma_b(float* c, const uint32_t* a, uint32_t b0, uint32_t b1) {
    asm volatile("mma.sync.aligned.m16n8k16.row.col.f32.bf16.bf16.f32 "
        "{%0,%1,%2,%3}, {%4,%5,%6,%7}, {%8,%9}, {%0,%1,%2,%3};"
        : "+f"(c[0]), "+f"(c[1]), "+f"(c[2]), "+f"(c[3])
        : "r"(a[0]), "r"(a[1]), "r"(a[2]), "r"(a[3]), "r"(b0), "r"(b1));
}

// ---------------- scratch (device globals: allocation-guard safe) -----------
__device__ float g_q[BATCH * HEADS * SEQ * DKV];
__device__ float g_k[BATCH * HEADS * SEQ * DKV];
__device__ float g_v[BATCH * HEADS * SEQ * DKV];
__device__ float g_attn[MTOT * DMODEL];
__device__ float g_bias[HEADS * BIAS_PAD];

// ---------------- T5 relative-position bias ---------------------------------
__global__ void bias_kernel(const float* __restrict__ table) {
    int i = blockIdx.x * blockDim.x + threadIdx.x;
    if (i >= HEADS * BIAS_PAD) return;
    int h = i / BIAS_PAD;
    int delta = (i % BIAS_PAD) - BIAS_CENTER;
    float v = 0.0f;
    int rp = delta < 0 ? -delta : delta;
    if (rp <= SEQ - 1) {
        int base = (delta > 0) ? 16 : 0;
        int bucket;
        if (rp < 8) {
            bucket = base + rp;
        } else {
            float ratio = logf((float)rp * 0.125f) / (float)2.772588722239781;
            int rpl = 8 + (int)(ratio * 8.0f);
            bucket = base + (rpl < 15 ? rpl : 15);
        }
        v = table[bucket * HEADS + h];
    }
    g_bias[i] = v;
}

// ---------------- bf16-split tensor-core GEMM -------------------------------
// C[4096,1024] = A[4096,1024] @ W[1024,1024], fp32 in/out, 2-term bf16 split.
// a_from_gattn: A = g_attn (device global, bound IN DEVICE CODE).
// qkv_mode: z = blockIdx.z selects W0/W1/W2, output -> g_q/g_k/g_v head layout.
// else: single W0, output -> outp row-major.
#define APITCH 80      // bytes per A smem row (32 bf16 padded -> conflict-free ldmatrix)
#define BPITCH 272     // bytes per B smem row (128 bf16 padded)
#define SM_AHI 0
#define SM_ALO 10240
#define SM_BHI 20480
#define SM_BLO 29184

__global__ __launch_bounds__(256) void gemm_bf16(const float* __restrict__ Aext,
                                                 int a_from_gattn, int qkv_mode,
                                                 const float* __restrict__ W0,
                                                 const float* __restrict__ W1,
                                                 const float* __restrict__ W2,
                                                 float* __restrict__ outp) {
    __shared__ __align__(16) char sm[2 * 10240 + 2 * 8704];   // 37888 B

    const float* A = a_from_gattn ? g_attn : Aext;

    int tid = threadIdx.x, lane = tid & 31, wid = tid >> 5;
    int wm = wid >> 2, wn = wid & 3;           // 2 x 4 warp grid
    int n0 = blockIdx.x * 128, m0 = blockIdx.y * 128;
    int z = blockIdx.z;
    const float* W = (z == 0) ? W0 : (z == 1) ? W1 : W2;

    uint32_t sb = smem_u32(sm);

    // fill-thread indices (constant across the 4 per-thread quads)
    int ac = (tid & 7) * 4;       // A col (float) within 32-wide chunk
    int bc = (tid & 31) * 4;      // B col (float) within 128-wide tile
    int ar0 = tid >> 3;           // A row base (+32 per i)
    int bk0 = tid >> 5;           // B k-row base (+8 per i)

    const float* Ap = A + (size_t)m0 * DMODEL;
    const float* Wp = W + n0;

    float4 a4[4], b4[4];
#pragma unroll
    for (int i = 0; i < 4; i++) {
        a4[i] = *(const float4*)(Ap + (size_t)(ar0 + i * 32) * DMODEL + ac);
        b4[i] = *(const float4*)(Wp + (size_t)(bk0 + i * 8) * DMODEL + bc);
    }

    float acc[4][4][4];
#pragma unroll
    for (int a = 0; a < 4; a++)
#pragma unroll
        for (int b = 0; b < 4; b++)
#pragma unroll
            for (int c = 0; c < 4; c++) acc[a][b][c] = 0.0f;

    // per-thread ldmatrix base addresses (constant across chunks)
    uint32_t aoff = (uint32_t)((wm * 64 + (lane & 15)) * APITCH + (lane >> 4) * 16);
    uint32_t boff = (uint32_t)(((lane & 7) + ((lane >> 3) & 1) * 8) * BPITCH
                               + (wn * 32 + (lane >> 4) * 8) * 2);

    for (int ch = 0; ch < 32; ch++) {
        // ---- convert + store staged regs to smem ----
#pragma unroll
        for (int i = 0; i < 4; i++) {
            float4 v = a4[i];
            uint32_t h01 = bfpack(v.x, v.y), h23 = bfpack(v.z, v.w);
            float l0 = v.x - __uint_as_float(h01 << 16);
            float l1 = v.y - __uint_as_float(h01 & 0xffff0000u);
            float l2 = v.z - __uint_as_float(h23 << 16);
            float l3 = v.w - __uint_as_float(h23 & 0xffff0000u);
            uint32_t q01 = bfpack(l0, l1), q23 = bfpack(l2, l3);
            char* p = sm + SM_AHI + (ar0 + i * 32) * APITCH + ac * 2;
            *(uint2*)p = make_uint2(h01, h23);
            *(uint2*)(p + (SM_ALO - SM_AHI)) = make_uint2(q01, q23);

            v = b4[i];
            h01 = bfpack(v.x, v.y); h23 = bfpack(v.z, v.w);
            l0 = v.x - __uint_as_float(h01 << 16);
            l1 = v.y - __uint_as_float(h01 & 0xffff0000u);
            l2 = v.z - __uint_as_float(h23 << 16);
            l3 = v.w - __uint_as_float(h23 & 0xffff0000u);
            q01 = bfpack(l0, l1); q23 = bfpack(l2, l3);
            char* pb = sm + SM_BHI + (bk0 + i * 8) * BPITCH + bc * 2;
            *(uint2*)pb = make_uint2(h01, h23);
            *(uint2*)(pb + (SM_BLO - SM_BHI)) = make_uint2(q01, q23);
        }
        __syncthreads();

        // ---- prefetch next chunk while computing this one ----
        if (ch < 31) {
            int k0n = (ch + 1) * 32;
#pragma unroll
            for (int i = 0; i < 4; i++) {
                a4[i] = *(const float4*)(Ap + (size_t)(ar0 + i * 32) * DMODEL + k0n + ac);
                b4[i] = *(const float4*)(Wp + (size_t)(k0n + bk0 + i * 8) * DMODEL + bc);
            }
        }

        // ---- tensor-core compute: 2 k-steps x (4m x 4n) x 3 split combos ----
#pragma unroll
        for (int ks = 0; ks < 2; ks++) {
            uint32_t ah[4][4], al[4][4], bh[2][4], bl[2][4];
#pragma unroll
            for (int mf = 0; mf < 4; mf++) {
                uint32_t ad = sb + SM_AHI + aoff + mf * (16 * APITCH) + ks * 32;
                ldm_x4(ah[mf], ad);
                ldm_x4(al[mf], ad + (SM_ALO - SM_AHI));
            }
#pragma unroll
            for (int nf2 = 0; nf2 < 2; nf2++) {
                uint32_t bd = sb + SM_BHI + boff + nf2 * 32 + ks * (16 * BPITCH);
                ldm_x4t(bh[nf2], bd);
                ldm_x4t(bl[nf2], bd + (SM_BLO - SM_BHI));
            }
#pragma unroll
            for (int mf = 0; mf < 4; mf++)
#pragma unroll
                for (int nf = 0; nf < 4; nf++) {
                    uint32_t b0 = bh[nf >> 1][(nf & 1) * 2];
                    uint32_t b1 = bh[nf >> 1][(nf & 1) * 2 + 1];
                    uint32_t c0 = bl[nf >> 1][(nf & 1) * 2];
                    uint32_t c1 = bl[nf >> 1][(nf & 1) * 2 + 1];
                    mma_b(acc[mf][nf], ah[mf], b0, b1);   // hi * hi
                    mma_b(acc[mf][nf], ah[mf], c0, c1);   // hi * lo
                    mma_b(acc[mf][nf], al[mf], b0, b1);   // lo * hi
                }
        }
        __syncthreads();
    }

    // ---- epilogue ----
    int g = lane >> 2, tg = lane & 3;
    float* dst = (z == 0) ? g_q : (z == 1) ? g_k : g_v;
#pragma unroll
    for (int mf = 0; mf < 4; mf++) {
        int r0 = m0 + wm * 64 + mf * 16 + g;
#pragma unroll
        for (int nf = 0; nf < 4; nf++) {
            int c = n0 + wn * 32 + nf * 8 + tg * 2;
            float2 vlo = make_float2(acc[mf][nf][0], acc[mf][nf][1]);
            float2 vhi = make_float2(acc[mf][nf][2], acc[mf][nf][3]);
            if (qkv_mode) {
                int h = c >> 6, d = c & 63;
#pragma unroll
                for (int half = 0; half < 2; half++) {
                    int r = r0 + half * 8;
                    int b = r >> 11, s = r & (SEQ - 1);
                    *(float2*)&dst[((((size_t)(b * HEADS + h)) * SEQ + s) << 6) + d] =
                        half ? vhi : vlo;
                }
            } else {
                *(float2*)&outp[(size_t)r0 * DMODEL + c] = vlo;
                *(float2*)&outp[(size_t)(r0 + 8) * DMODEL + c] = vhi;
            }
        }
    }
}

// ---------------- flash attention: 1 thread = 1 q row, FFMA2 ---------------
__global__ __launch_bounds__(128) void attn_kernel() {
    int tid = threadIdx.x;
    int qt = blockIdx.x, h = blockIdx.y, b = blockIdx.z;
    int bh = b * HEADS + h;
    int q0 = qt * QR;
    int qi = q0 + tid;

    __shared__ __align__(16) u64 Ks2[KT * 32];
    __shared__ __align__(16) u64 Vs2[KT * 32];
    __shared__ float Ss[KT * QR];
    __shared__ float bias_s[KT + QR];

    u64 q2[32], o2[32];
    const u64* qp = (const u64*)(g_q + (((size_t)bh * SEQ + qi) << 6));
#pragma unroll
    for (int i = 0; i < 32; i++) {
        q2[i] = qp[i];
        o2[i] = 0ull;
    }

    float m = -1e30f, l = 0.0f;

    for (int kt = 0; kt < SEQ / KT; kt++) {
        int kbase = kt * KT;
        const float4* kp = (const float4*)(g_k + (((size_t)bh * SEQ + kbase) << 6));
        const float4* vp = (const float4*)(g_v + (((size_t)bh * SEQ + kbase) << 6));

        __syncthreads();
#pragma unroll
        for (int i = 0; i < 4; i++) {
            ((float4*)Ks2)[tid + i * 128] = kp[tid + i * 128];
            ((float4*)Vs2)[tid + i * 128] = vp[tid + i * 128];
        }
        {
            const float* bb = g_bias + h * BIAS_PAD + (BIAS_CENTER - (QR - 1)) - q0 + kbase;
            bias_s[tid] = bb[tid];
            if (tid < KT) bias_s[QR + tid] = bb[QR + tid];
        }
        __syncthreads();

        float mt = -1e30f;
#pragma unroll 4
        for (int j = 0; j < KT; j++) {
            u64 s0 = 0ull, s1 = 0ull, s2 = 0ull, s3 = 0ull;
            const ulonglong2* kr2 = (const ulonglong2*)&Ks2[j * 32];
#pragma unroll
            for (int t = 0; t < 4; t++) {
                ulonglong2 ka = kr2[t];
                ulonglong2 kb = kr2[t + 4];
                ulonglong2 kc = kr2[t + 8];
                ulonglong2 kd = kr2[t + 12];
                fma2(s0, q2[2 * t],      ka.x); fma2(s0, q2[2 * t + 1],  ka.y);
                fma2(s1, q2[8 + 2 * t],  kb.x); fma2(s1, q2[9 + 2 * t],  kb.y);
                fma2(s2, q2[16 + 2 * t], kc.x); fma2(s2, q2[17 + 2 * t], kc.y);
                fma2(s3, q2[24 + 2 * t], kd.x); fma2(s3, q2[25 + 2 * t], kd.y);
            }
            add2(s0, s1); add2(s2, s3); add2(s0, s2);
            float2 f = up2(s0);
            float sj = f.x + f.y + bias_s[j - tid + (QR - 1)];
            Ss[j * QR + tid] = sj;
            mt = fmaxf(mt, sj);
        }

        float mnew = fmaxf(m, mt);
        float corr = __expf(m - mnew);
        u64 c2 = pk2(corr, corr);
#pragma unroll
        for (int i = 0; i < 32; i++) o2[i] = mul2(o2[i], c2);

        float ssum = 0.f;
#pragma unroll 4
        for (int j = 0; j < KT; j++) {
            float p = __expf(Ss[j * QR + tid] - mnew);
            ssum += p;
            u64 p2 = pk2(p, p);
            const ulonglong2* vr2 = (const ulonglong2*)&Vs2[j * 32];
#pragma unroll
            for (int t = 0; t < 16; t++) {
                ulonglong2 vv = vr2[t];
                fma2(o2[2 * t],     p2, vv.x);
                fma2(o2[2 * t + 1], p2, vv.y);
            }
        }
        l = l * corr + ssum;
        m = mnew;
    }

    float inv = 1.0f / l;
    u64 inv2 = pk2(inv, inv);
    ulonglong2* op = (ulonglong2*)(g_attn + ((size_t)b * SEQ + qi) * DMODEL + h * DKV);
#pragma unroll
    for (int t = 0; t < 16; t++) {
        ulonglong2 w;
        w.x = mul2(o2[2 * t],     inv2);
        w.y = mul2(o2[2 * t + 1], inv2);
        op[t] = w;
    }
}

// ---------------- launcher ---------------------------------------------------
extern "C" void kernel_launch(void* const* d_in, const int* in_sizes, int n_in,
                              void* d_out, int out_size) {
    const float* hidden = (const float*)d_in[0];
    const float* Wq     = (const float*)d_in[1];
    const float* Wk     = (const float*)d_in[2];
    const float* Wv     = (const float*)d_in[3];
    const float* Wo     = (const float*)d_in[4];
    const float* table  = (const float*)d_in[5];
    float* out = (float*)d_out;

    bias_kernel<<<(HEADS * BIAS_PAD + 255) / 256, 256>>>(table);

    // fused QKV projection on tensor cores: z = 0/1/2 -> Wq/Wk/Wv
    dim3 qkv_grid(DMODEL / 128, MTOT / 128, 3);
    gemm_bf16<<<qkv_grid, 256>>>(hidden, 0, 1, Wq, Wk, Wv, nullptr);

    attn_kernel<<<dim3(SEQ / QR, HEADS, BATCH), 128>>>();

    // output projection: A = g_attn (bound in device code via flag)
    dim3 o_grid(DMODEL / 128, MTOT / 128, 1);
    gemm_bf16<<<o_grid, 256>>>(nullptr, 1, 0, Wo, Wo, Wo, out);
}

// round 7
// speedup vs baseline: 3.3081x; 2.2950x over previous
#include <cuda_runtime.h>
#include <cstdint>

#define BATCH   2
#define HEADS   16
#define SEQ     2048
#define DKV     64
#define DMODEL  1024
#define MTOT    (BATCH * SEQ)      // 4096 rows
#define BIAS_PAD    4352
#define BIAS_CENTER 2176

// ---------------- bf16 pack + tensor-core helpers ---------------------------
// returns packed b16x2: low half = bf16(lo_e), high half = bf16(hi_e)
__device__ __forceinline__ uint32_t bfpack(float lo_e, float hi_e) {
    uint32_t r; asm("cvt.rn.bf16x2.f32 %0, %1, %2;" : "=r"(r) : "f"(hi_e), "f"(lo_e));
    return r;
}
__device__ __forceinline__ uint32_t smem_u32(const void* p) {
    uint32_t a;
    asm("{ .reg .u64 t; cvta.to.shared.u64 t, %1; cvt.u32.u64 %0, t; }" : "=r"(a) : "l"(p));
    return a;
}
__device__ __forceinline__ void ldm_x4(uint32_t* r, uint32_t addr) {
    asm volatile("ldmatrix.sync.aligned.m8n8.x4.shared.b16 {%0,%1,%2,%3}, [%4];"
        : "=r"(r[0]), "=r"(r[1]), "=r"(r[2]), "=r"(r[3]) : "r"(addr));
}
__device__ __forceinline__ void ldm_x4t(uint32_t* r, uint32_t addr) {
    asm volatile("ldmatrix.sync.aligned.m8n8.x4.trans.shared.b16 {%0,%1,%2,%3}, [%4];"
        : "=r"(r[0]), "=r"(r[1]), "=r"(r[2]), "=r"(r[3]) : "r"(addr));
}
__device__ __forceinline__ void mma_b(float* c, const uint32_t* a, uint32_t b0, uint32_t b1) {
    asm volatile("mma.sync.aligned.m16n8k16.row.col.f32.bf16.bf16.f32 "
        "{%0,%1,%2,%3}, {%4,%5,%6,%7}, {%8,%9}, {%0,%1,%2,%3};"
        : "+f"(c[0]), "+f"(c[1]), "+f"(c[2]), "+f"(c[3])
        : "r"(a[0]), "r"(a[1]), "r"(a[2]), "r"(a[3]), "r"(b0), "r"(b1));
}

// ---------------- scratch (device globals: allocation-guard safe) -----------
__device__ float g_q[BATCH * HEADS * SEQ * DKV];
__device__ float g_k[BATCH * HEADS * SEQ * DKV];
__device__ float g_v[BATCH * HEADS * SEQ * DKV];
__device__ float g_attn[MTOT * DMODEL];
__device__ float g_bias[HEADS * BIAS_PAD];

// ---------------- T5 relative-position bias ---------------------------------
__global__ void bias_kernel(const float* __restrict__ table) {
    int i = blockIdx.x * blockDim.x + threadIdx.x;
    if (i >= HEADS * BIAS_PAD) return;
    int h = i / BIAS_PAD;
    int delta = (i % BIAS_PAD) - BIAS_CENTER;
    float v = 0.0f;
    int rp = delta < 0 ? -delta : delta;
    if (rp <= SEQ - 1) {
        int base = (delta > 0) ? 16 : 0;
        int bucket;
        if (rp < 8) {
            bucket = base + rp;
        } else {
            float ratio = logf((float)rp * 0.125f) / (float)2.772588722239781;
            int rpl = 8 + (int)(ratio * 8.0f);
            bucket = base + (rpl < 15 ? rpl : 15);
        }
        v = table[bucket * HEADS + h];
    }
    g_bias[i] = v;
}

// ---------------- bf16-split tensor-core GEMM (validated round 6) -----------
#define APITCH 80
#define BPITCH 272
#define SM_AHI 0
#define SM_ALO 10240
#define SM_BHI 20480
#define SM_BLO 29184

__global__ __launch_bounds__(256) void gemm_bf16(const float* __restrict__ Aext,
                                                 int a_from_gattn, int qkv_mode,
                                                 const float* __restrict__ W0,
                                                 const float* __restrict__ W1,
                                                 const float* __restrict__ W2,
                                                 float* __restrict__ outp) {
    __shared__ __align__(16) char sm[2 * 10240 + 2 * 8704];

    const float* A = a_from_gattn ? g_attn : Aext;

    int tid = threadIdx.x, lane = tid & 31, wid = tid >> 5;
    int wm = wid >> 2, wn = wid & 3;
    int n0 = blockIdx.x * 128, m0 = blockIdx.y * 128;
    int z = blockIdx.z;
    const float* W = (z == 0) ? W0 : (z == 1) ? W1 : W2;

    uint32_t sb = smem_u32(sm);

    int ac = (tid & 7) * 4;
    int bc = (tid & 31) * 4;
    int ar0 = tid >> 3;
    int bk0 = tid >> 5;

    const float* Ap = A + (size_t)m0 * DMODEL;
    const float* Wp = W + n0;

    float4 a4[4], b4[4];
#pragma unroll
    for (int i = 0; i < 4; i++) {
        a4[i] = *(const float4*)(Ap + (size_t)(ar0 + i * 32) * DMODEL + ac);
        b4[i] = *(const float4*)(Wp + (size_t)(bk0 + i * 8) * DMODEL + bc);
    }

    float acc[4][4][4];
#pragma unroll
    for (int a = 0; a < 4; a++)
#pragma unroll
        for (int b = 0; b < 4; b++)
#pragma unroll
            for (int c = 0; c < 4; c++) acc[a][b][c] = 0.0f;

    uint32_t aoff = (uint32_t)((wm * 64 + (lane & 15)) * APITCH + (lane >> 4) * 16);
    uint32_t boff = (uint32_t)(((lane & 7) + ((lane >> 3) & 1) * 8) * BPITCH
                               + (wn * 32 + (lane >> 4) * 8) * 2);

    for (int ch = 0; ch < 32; ch++) {
#pragma unroll
        for (int i = 0; i < 4; i++) {
            float4 v = a4[i];
            uint32_t h01 = bfpack(v.x, v.y), h23 = bfpack(v.z, v.w);
            float l0 = v.x - __uint_as_float(h01 << 16);
            float l1 = v.y - __uint_as_float(h01 & 0xffff0000u);
            float l2 = v.z - __uint_as_float(h23 << 16);
            float l3 = v.w - __uint_as_float(h23 & 0xffff0000u);
            uint32_t q01 = bfpack(l0, l1), q23 = bfpack(l2, l3);
            char* p = sm + SM_AHI + (ar0 + i * 32) * APITCH + ac * 2;
            *(uint2*)p = make_uint2(h01, h23);
            *(uint2*)(p + (SM_ALO - SM_AHI)) = make_uint2(q01, q23);

            v = b4[i];
            h01 = bfpack(v.x, v.y); h23 = bfpack(v.z, v.w);
            l0 = v.x - __uint_as_float(h01 << 16);
            l1 = v.y - __uint_as_float(h01 & 0xffff0000u);
            l2 = v.z - __uint_as_float(h23 << 16);
            l3 = v.w - __uint_as_float(h23 & 0xffff0000u);
            q01 = bfpack(l0, l1); q23 = bfpack(l2, l3);
            char* pb = sm + SM_BHI + (bk0 + i * 8) * BPITCH + bc * 2;
            *(uint2*)pb = make_uint2(h01, h23);
            *(uint2*)(pb + (SM_BLO - SM_BHI)) = make_uint2(q01, q23);
        }
        __syncthreads();

        if (ch < 31) {
            int k0n = (ch + 1) * 32;
#pragma unroll
            for (int i = 0; i < 4; i++) {
                a4[i] = *(const float4*)(Ap + (size_t)(ar0 + i * 32) * DMODEL + k0n + ac);
                b4[i] = *(const float4*)(Wp + (size_t)(k0n + bk0 + i * 8) * DMODEL + bc);
            }
        }

#pragma unroll
        for (int ks = 0; ks < 2; ks++) {
            uint32_t ah[4][4], al[4][4], bh[2][4], bl[2][4];
#pragma unroll
            for (int mf = 0; mf < 4; mf++) {
                uint32_t ad = sb + SM_AHI + aoff + mf * (16 * APITCH) + ks * 32;
                ldm_x4(ah[mf], ad);
                ldm_x4(al[mf], ad + (SM_ALO - SM_AHI));
            }
#pragma unroll
            for (int nf2 = 0; nf2 < 2; nf2++) {
                uint32_t bd = sb + SM_BHI + boff + nf2 * 32 + ks * (16 * BPITCH);
                ldm_x4t(bh[nf2], bd);
                ldm_x4t(bl[nf2], bd + (SM_BLO - SM_BHI));
            }
#pragma unroll
            for (int mf = 0; mf < 4; mf++)
#pragma unroll
                for (int nf = 0; nf < 4; nf++) {
                    uint32_t b0 = bh[nf >> 1][(nf & 1) * 2];
                    uint32_t b1 = bh[nf >> 1][(nf & 1) * 2 + 1];
                    uint32_t c0 = bl[nf >> 1][(nf & 1) * 2];
                    uint32_t c1 = bl[nf >> 1][(nf & 1) * 2 + 1];
                    mma_b(acc[mf][nf], ah[mf], b0, b1);
                    mma_b(acc[mf][nf], ah[mf], c0, c1);
                    mma_b(acc[mf][nf], al[mf], b0, b1);
                }
        }
        __syncthreads();
    }

    int g = lane >> 2, tg = lane & 3;
    float* dst = (z == 0) ? g_q : (z == 1) ? g_k : g_v;
#pragma unroll
    for (int mf = 0; mf < 4; mf++) {
        int r0 = m0 + wm * 64 + mf * 16 + g;
#pragma unroll
        for (int nf = 0; nf < 4; nf++) {
            int c = n0 + wn * 32 + nf * 8 + tg * 2;
            float2 vlo = make_float2(acc[mf][nf][0], acc[mf][nf][1]);
            float2 vhi = make_float2(acc[mf][nf][2], acc[mf][nf][3]);
            if (qkv_mode) {
                int h = c >> 6, d = c & 63;
#pragma unroll
                for (int half = 0; half < 2; half++) {
                    int r = r0 + half * 8;
                    int b = r >> 11, s = r & (SEQ - 1);
                    *(float2*)&dst[((((size_t)(b * HEADS + h)) * SEQ + s) << 6) + d] =
                        half ? vhi : vlo;
                }
            } else {
                *(float2*)&outp[(size_t)r0 * DMODEL + c] = vlo;
                *(float2*)&outp[(size_t)(r0 + 8) * DMODEL + c] = vhi;
            }
        }
    }
}

// ---------------- tensor-core flash attention --------------------------------
// CTA: 128 q-rows x one (b,h); 8 warps x m16 slices; K-tiles of 64.
// QK^T + bias -> online softmax in C-fragment layout -> P (registers) @ V.
// All MMA operands use 2-term bf16 split (3 MMAs per logical product).
#define KTILE 64
#define PITCH 144          // 64 bf16 = 128 B + 16 pad -> conflict-free ldmatrix
#define AT_QLO 18432       // Q lo plane offset (also V hi base when reused)
#define AT_KLO 9216
#define AT_VHI 18432
#define AT_VLO 27648

__global__ __launch_bounds__(256) void attn_tc() {
    __shared__ __align__(16) char smA[36864];
    __shared__ float bias_s[192];

    int tid = threadIdx.x, lane = tid & 31, w = tid >> 5;
    int h = blockIdx.y, b = blockIdx.z;
    int bh = b * HEADS + h;
    int q0 = blockIdx.x * 128;

    uint32_t sb = smem_u32(smA);

    // ---- stage Q tile (128 x 64) as bf16 hi/lo ----
    {
        int qrow = tid >> 1, qc0 = (tid & 1) * 32;
        const float* qp = g_q + ((size_t)bh * SEQ + q0 + qrow) * 64 + qc0;
#pragma unroll
        for (int i = 0; i < 8; i++) {
            float4 v = *(const float4*)(qp + i * 4);
            uint32_t h01 = bfpack(v.x, v.y), h23 = bfpack(v.z, v.w);
            float l0 = v.x - __uint_as_float(h01 << 16);
            float l1 = v.y - __uint_as_float(h01 & 0xffff0000u);
            float l2 = v.z - __uint_as_float(h23 << 16);
            float l3 = v.w - __uint_as_float(h23 & 0xffff0000u);
            uint32_t q01 = bfpack(l0, l1), q23 = bfpack(l2, l3);
            char* p = smA + qrow * PITCH + (qc0 + i * 4) * 2;
            *(uint2*)p = make_uint2(h01, h23);
            *(uint2*)(p + AT_QLO) = make_uint2(q01, q23);
        }
    }
    __syncthreads();

    // ---- Q fragments to registers (4 k-steps, hi/lo) ----
    uint32_t qh[4][4], ql[4][4];
#pragma unroll
    for (int ks = 0; ks < 4; ks++) {
        uint32_t ad = sb + (w * 16 + (lane & 15)) * PITCH + (lane >> 4) * 16 + ks * 32;
        ldm_x4(qh[ks], ad);
        ldm_x4(ql[ks], ad + AT_QLO);
    }

    // ---- prefetch K/V tile 0 ----
    int krow = tid >> 2, kc0 = (tid & 3) * 16;
    float4 pk4[4], pv4[4];
    {
        const float* kp = g_k + ((size_t)bh * SEQ + krow) * 64 + kc0;
        const float* vp = g_v + ((size_t)bh * SEQ + krow) * 64 + kc0;
#pragma unroll
        for (int i = 0; i < 4; i++) {
            pk4[i] = *(const float4*)(kp + i * 4);
            pv4[i] = *(const float4*)(vp + i * 4);
        }
    }
    __syncthreads();   // all warps done reading Q smem before K/V overwrite

    float Oacc[8][4];
#pragma unroll
    for (int nf = 0; nf < 8; nf++)
#pragma unroll
        for (int j = 0; j < 4; j++) Oacc[nf][j] = 0.0f;

    float m_lo = -1e30f, m_hi = -1e30f, l_lo = 0.0f, l_hi = 0.0f;
    int rq = lane >> 2, cq = 2 * (lane & 3);
    int rt = w * 16 + rq;

    for (int kt = 0; kt < SEQ / KTILE; kt++) {
        int kbase = kt * KTILE;

        // ---- store staged K/V to smem (split) ----
#pragma unroll
        for (int i = 0; i < 4; i++) {
            float4 v = pk4[i];
            uint32_t h01 = bfpack(v.x, v.y), h23 = bfpack(v.z, v.w);
            float l0 = v.x - __uint_as_float(h01 << 16);
            float l1 = v.y - __uint_as_float(h01 & 0xffff0000u);
            float l2 = v.z - __uint_as_float(h23 << 16);
            float l3 = v.w - __uint_as_float(h23 & 0xffff0000u);
            uint32_t q01 = bfpack(l0, l1), q23 = bfpack(l2, l3);
            char* p = smA + krow * PITCH + (kc0 + i * 4) * 2;
            *(uint2*)p = make_uint2(h01, h23);
            *(uint2*)(p + AT_KLO) = make_uint2(q01, q23);

            v = pv4[i];
            h01 = bfpack(v.x, v.y); h23 = bfpack(v.z, v.w);
            l0 = v.x - __uint_as_float(h01 << 16);
            l1 = v.y - __uint_as_float(h01 & 0xffff0000u);
            l2 = v.z - __uint_as_float(h23 << 16);
            l3 = v.w - __uint_as_float(h23 & 0xffff0000u);
            q01 = bfpack(l0, l1); q23 = bfpack(l2, l3);
            char* pv = smA + AT_VHI + krow * PITCH + (kc0 + i * 4) * 2;
            *(uint2*)pv = make_uint2(h01, h23);
            *(uint2*)(pv + (AT_VLO - AT_VHI)) = make_uint2(q01, q23);
        }
        if (tid < 192)
            bias_s[tid] = g_bias[h * BIAS_PAD + BIAS_CENTER + kbase - q0 + tid - 127];
        __syncthreads();

        // ---- prefetch next tile ----
        if (kt < SEQ / KTILE - 1) {
            const float* kp = g_k + ((size_t)bh * SEQ + kbase + KTILE + krow) * 64 + kc0;
            const float* vp = g_v + ((size_t)bh * SEQ + kbase + KTILE + krow) * 64 + kc0;
#pragma unroll
            for (int i = 0; i < 4; i++) {
                pk4[i] = *(const float4*)(kp + i * 4);
                pv4[i] = *(const float4*)(vp + i * 4);
            }
        }

        // ---- S = Q . K^T (3-split) ----
        float Sv[8][4];
#pragma unroll
        for (int nf = 0; nf < 8; nf++)
#pragma unroll
            for (int j = 0; j < 4; j++) Sv[nf][j] = 0.0f;

#pragma unroll
        for (int nf2 = 0; nf2 < 4; nf2++) {
#pragma unroll
            for (int ks = 0; ks < 4; ks++) {
                uint32_t kh4[4], kl4[4];
                uint32_t ad = sb + (nf2 * 16 + (lane & 7) + ((lane >> 4) << 3)) * PITCH
                              + ((lane >> 3) & 1) * 16 + ks * 32;
                ldm_x4(kh4, ad);
                ldm_x4(kl4, ad + AT_KLO);
                mma_b(Sv[2 * nf2],     qh[ks], kh4[0], kh4[1]);
                mma_b(Sv[2 * nf2],     qh[ks], kl4[0], kl4[1]);
                mma_b(Sv[2 * nf2],     ql[ks], kh4[0], kh4[1]);
                mma_b(Sv[2 * nf2 + 1], qh[ks], kh4[2], kh4[3]);
                mma_b(Sv[2 * nf2 + 1], qh[ks], kl4[2], kl4[3]);
                mma_b(Sv[2 * nf2 + 1], ql[ks], kh4[2], kh4[3]);
            }
        }

        // ---- bias + online softmax (two rows per thread) ----
        const float* bw = bias_s + 127 - rt;
        float mt_lo = -1e30f, mt_hi = -1e30f;
#pragma unroll
        for (int nf = 0; nf < 8; nf++) {
            int c = nf * 8 + cq;
            Sv[nf][0] += bw[c];
            Sv[nf][1] += bw[c + 1];
            Sv[nf][2] += bw[c - 8];
            Sv[nf][3] += bw[c - 7];
            mt_lo = fmaxf(mt_lo, fmaxf(Sv[nf][0], Sv[nf][1]));
            mt_hi = fmaxf(mt_hi, fmaxf(Sv[nf][2], Sv[nf][3]));
        }
        mt_lo = fmaxf(mt_lo, __shfl_xor_sync(0xffffffffu, mt_lo, 1));
        mt_lo = fmaxf(mt_lo, __shfl_xor_sync(0xffffffffu, mt_lo, 2));
        mt_hi = fmaxf(mt_hi, __shfl_xor_sync(0xffffffffu, mt_hi, 1));
        mt_hi = fmaxf(mt_hi, __shfl_xor_sync(0xffffffffu, mt_hi, 2));

        float mn_lo = fmaxf(m_lo, mt_lo), mn_hi = fmaxf(m_hi, mt_hi);
        float corr_lo = __expf(m_lo - mn_lo), corr_hi = __expf(m_hi - mn_hi);
        m_lo = mn_lo; m_hi = mn_hi;

        float ps_lo = 0.0f, ps_hi = 0.0f;
#pragma unroll
        for (int nf = 0; nf < 8; nf++) {
            Sv[nf][0] = __expf(Sv[nf][0] - mn_lo);
            Sv[nf][1] = __expf(Sv[nf][1] - mn_lo);
            Sv[nf][2] = __expf(Sv[nf][2] - mn_hi);
            Sv[nf][3] = __expf(Sv[nf][3] - mn_hi);
            ps_lo += Sv[nf][0] + Sv[nf][1];
            ps_hi += Sv[nf][2] + Sv[nf][3];
        }
        ps_lo += __shfl_xor_sync(0xffffffffu, ps_lo, 1);
        ps_lo += __shfl_xor_sync(0xffffffffu, ps_lo, 2);
        ps_hi += __shfl_xor_sync(0xffffffffu, ps_hi, 1);
        ps_hi += __shfl_xor_sync(0xffffffffu, ps_hi, 2);
        l_lo = l_lo * corr_lo + ps_lo;
        l_hi = l_hi * corr_hi + ps_hi;

#pragma unroll
        for (int nf = 0; nf < 8; nf++) {
            Oacc[nf][0] *= corr_lo; Oacc[nf][1] *= corr_lo;
            Oacc[nf][2] *= corr_hi; Oacc[nf][3] *= corr_hi;
        }

        // ---- O += P . V (P repacked from registers, 3-split) ----
#pragma unroll
        for (int ks = 0; ks < 4; ks++) {
            uint32_t pa_h[4], pa_l[4];
            pa_h[0] = bfpack(Sv[2 * ks][0], Sv[2 * ks][1]);
            pa_h[1] = bfpack(Sv[2 * ks][2], Sv[2 * ks][3]);
            pa_h[2] = bfpack(Sv[2 * ks + 1][0], Sv[2 * ks + 1][1]);
            pa_h[3] = bfpack(Sv[2 * ks + 1][2], Sv[2 * ks + 1][3]);
            pa_l[0] = bfpack(Sv[2 * ks][0] - __uint_as_float(pa_h[0] << 16),
                             Sv[2 * ks][1] - __uint_as_float(pa_h[0] & 0xffff0000u));
            pa_l[1] = bfpack(Sv[2 * ks][2] - __uint_as_float(pa_h[1] << 16),
                             Sv[2 * ks][3] - __uint_as_float(pa_h[1] & 0xffff0000u));
            pa_l[2] = bfpack(Sv[2 * ks + 1][0] - __uint_as_float(pa_h[2] << 16),
                             Sv[2 * ks + 1][1] - __uint_as_float(pa_h[2] & 0xffff0000u));
            pa_l[3] = bfpack(Sv[2 * ks + 1][2] - __uint_as_float(pa_h[3] << 16),
                             Sv[2 * ks + 1][3] - __uint_as_float(pa_h[3] & 0xffff0000u));
#pragma unroll
            for (int nf2 = 0; nf2 < 4; nf2++) {
                uint32_t vh4[4], vl4[4];
                uint32_t ad = sb + AT_VHI
                            + (ks * 16 + (lane & 7) + ((lane >> 3) & 1) * 8) * PITCH
                            + (nf2 * 16 + (lane >> 4) * 8) * 2;
                ldm_x4t(vh4, ad);
                ldm_x4t(vl4, ad + (AT_VLO - AT_VHI));
                mma_b(Oacc[2 * nf2],     pa_h, vh4[0], vh4[1]);
                mma_b(Oacc[2 * nf2],     pa_h, vl4[0], vl4[1]);
                mma_b(Oacc[2 * nf2],     pa_l, vh4[0], vh4[1]);
                mma_b(Oacc[2 * nf2 + 1], pa_h, vh4[2], vh4[3]);
                mma_b(Oacc[2 * nf2 + 1], pa_h, vl4[2], vl4[3]);
                mma_b(Oacc[2 * nf2 + 1], pa_l, vh4[2], vh4[3]);
            }
        }
        __syncthreads();   // compute done before next tile's smem store
    }

    // ---- epilogue: O / l -> g_attn [b][q][h*64+d] ----
    float inv_lo = 1.0f / l_lo, inv_hi = 1.0f / l_hi;
    float* o0 = g_attn + ((size_t)b * SEQ + q0 + rt) * DMODEL + h * DKV;
#pragma unroll
    for (int nf = 0; nf < 8; nf++) {
        int c = nf * 8 + cq;
        *(float2*)(o0 + c) = make_float2(Oacc[nf][0] * inv_lo, Oacc[nf][1] * inv_lo);
        *(float2*)(o0 + 8 * DMODEL + c) = make_float2(Oacc[nf][2] * inv_hi, Oacc[nf][3] * inv_hi);
    }
}

// ---------------- launcher ---------------------------------------------------
extern "C" void kernel_launch(void* const* d_in, const int* in_sizes, int n_in,
                              void* d_out, int out_size) {
    const float* hidden = (const float*)d_in[0];
    const float* Wq     = (const float*)d_in[1];
    const float* Wk     = (const float*)d_in[2];
    const float* Wv     = (const float*)d_in[3];
    const float* Wo     = (const float*)d_in[4];
    const float* table  = (const float*)d_in[5];
    float* out = (float*)d_out;

    bias_kernel<<<(HEADS * BIAS_PAD + 255) / 256, 256>>>(table);

    // fused QKV projection on tensor cores: z = 0/1/2 -> Wq/Wk/Wv
    dim3 qkv_grid(DMODEL / 128, MTOT / 128, 3);
    gemm_bf16<<<qkv_grid, 256>>>(hidden, 0, 1, Wq, Wk, Wv, nullptr);

    attn_tc<<<dim3(SEQ / 128, HEADS, BATCH), 256>>>();

    // output projection: A = g_attn (bound in device code via flag)
    dim3 o_grid(DMODEL / 128, MTOT / 128, 1);
    gemm_bf16<<<o_grid, 256>>>(nullptr, 1, 0, Wo, Wo, Wo, out);
}